// round 12
// baseline (speedup 1.0000x reference)
#include <cuda_runtime.h>

// Problem constants
#define Nv    20000
#define Tt    32
#define Ee    640000
#define Cc    10
#define Kk    5
#define PADc  2
#define CAP   128      // bucket capacity per node (mean deg 32; P(>=128) ~ e^-81)
#define MAXG  512
#define NTH   256
#define NUNITS 2500    // Nv/8 work units (8 nodes per warp per unit)

// ---------------- static device scratch (no allocs allowed) ----------------
__device__ int   g_cnt[Nv];              // per-node degree / bucket cursor
__device__ int   g_adj[Nv * CAP];        // bucketed adjacency (src per dst)
__device__ float g_xn[Nv * Tt];          // normalized x of current layer
__device__ float g_cm[(Nv + 1) * Tt];    // conv+max message (+row Nv:永zero)
__device__ float g_x[Nv * Tt];           // layer-0 output
__device__ float g_stat0[64];            // layer-0 sum / sumsq per t
__device__ float g_stat1[64];            // layer-1 sum / sumsq per t
__device__ float g_out3[3];              // output partial sums
__device__ int   g_ctrA, g_ctrB;         // work-steal counters (aggr phases)

// -------- device-wide barrier: monotonic epoch, self-resetting arrive ------
__device__ unsigned g_bar_arrive;          // zero-init; reset by last arriver
__device__ volatile unsigned g_bar_epoch;  // monotonic across replays

__device__ __forceinline__ void gsync() {
    __syncthreads();
    if (threadIdx.x == 0) {
        __threadfence();
        unsigned e = g_bar_epoch;
        if (atomicAdd(&g_bar_arrive, 1u) == gridDim.x - 1u) {
            g_bar_arrive = 0u;
            __threadfence();
            g_bar_epoch = e + 1u;
        } else {
            while (g_bar_epoch == e) { __nanosleep(64); }
        }
        __threadfence();
    }
    __syncthreads();
}

// 2-node interleaved float4 gather: 8 lanes per node pair, lane covers
// t = sub*4 .. sub*4+3 for BOTH nodes. 10 independent loads per step.
__device__ __forceinline__ void gather4x2(int deg0, int deg1, int base0, int base1,
                                          int sub, float4& r0, float4& r1) {
    float4 A0 = make_float4(0.f, 0.f, 0.f, 0.f);
    float4 A1 = make_float4(0.f, 0.f, 0.f, 0.f);
    const int mx = (deg0 > deg1) ? deg0 : deg1;
    for (int k = 0; k < mx; k += 4) {
        int4 ia = (k < deg0) ? *(const int4*)&g_adj[base0 + k] : make_int4(Nv, Nv, Nv, Nv);
        int4 ib = (k < deg1) ? *(const int4*)&g_adj[base1 + k] : make_int4(Nv, Nv, Nv, Nv);
        int a0 = (k + 0 < deg0) ? ia.x : Nv;
        int a1 = (k + 1 < deg0) ? ia.y : Nv;
        int a2 = (k + 2 < deg0) ? ia.z : Nv;
        int a3 = (k + 3 < deg0) ? ia.w : Nv;
        int b0 = (k + 0 < deg1) ? ib.x : Nv;
        int b1 = (k + 1 < deg1) ? ib.y : Nv;
        int b2 = (k + 2 < deg1) ? ib.z : Nv;
        int b3 = (k + 3 < deg1) ? ib.w : Nv;
        const float4 u0 = *(const float4*)&g_cm[a0 * Tt + sub * 4];
        const float4 u1 = *(const float4*)&g_cm[a1 * Tt + sub * 4];
        const float4 u2 = *(const float4*)&g_cm[a2 * Tt + sub * 4];
        const float4 u3 = *(const float4*)&g_cm[a3 * Tt + sub * 4];
        const float4 w0 = *(const float4*)&g_cm[b0 * Tt + sub * 4];
        const float4 w1 = *(const float4*)&g_cm[b1 * Tt + sub * 4];
        const float4 w2 = *(const float4*)&g_cm[b2 * Tt + sub * 4];
        const float4 w3 = *(const float4*)&g_cm[b3 * Tt + sub * 4];
        A0.x += (u0.x + u1.x) + (u2.x + u3.x);
        A0.y += (u0.y + u1.y) + (u2.y + u3.y);
        A0.z += (u0.z + u1.z) + (u2.z + u3.z);
        A0.w += (u0.w + u1.w) + (u2.w + u3.w);
        A1.x += (w0.x + w1.x) + (w2.x + w3.x);
        A1.y += (w0.y + w1.y) + (w2.y + w3.y);
        A1.z += (w0.z + w1.z) + (w2.z + w3.z);
        A1.w += (w0.w + w1.w) + (w2.w + w3.w);
    }
    r0 = A0;
    r1 = A1;
}

// ---------------- the whole model as one persistent kernel ----------------
__global__ void __launch_bounds__(NTH, 4) sage_fused(
    const float* __restrict__ x,     // [N,T]
    const float* __restrict__ convW, // [L,C,1,K]
    const float* __restrict__ convb, // [L,C]
    const float* __restrict__ alpha, // [L,T]
    const float* __restrict__ scale, // [L,T]
    const float* __restrict__ shift, // [L,T]
    const float* __restrict__ Wout,  // [3,N]
    const float* __restrict__ bout,  // [3]
    const int*   __restrict__ ei,    // [2,E]
    float*       __restrict__ out)   // [3]
{
    const int tid  = threadIdx.x;
    const int lane = tid & 31;
    const int w    = tid >> 5;
    const int sub  = lane & 7;   // position within 8-lane node group
    const int grp  = lane >> 3;  // node group 0..3 within warp
    const int b    = blockIdx.x;
    const int G    = gridDim.x;
    const int nthreads = G * NTH;
    const int gtid     = b * NTH + tid;
    const int nwarps   = G * 8;
    const int gwarp    = b * 8 + w;

    __shared__ float sh[8][64];
    __shared__ float sm[Tt], smul[Tt], ssh[Tt];
    __shared__ float sW[Cc * Kk];
    __shared__ float sbias[Cc];
    __shared__ float shp[8][3];

    // NOTE: all mutable global scratch (g_cnt, g_stat*, g_out3, g_ctr*) is
    // zero on entry: zero-initialized at load, and each replay re-zeroes it
    // in the phase after last use. No P0 zeroing phase / barrier needed.

    // ---- P1: single-pass bucketed adjacency build + layer-0 column stats ----
    for (int e = gtid; e < Ee; e += nthreads * 4) {
        int ss[4], dd[4];
#pragma unroll
        for (int k = 0; k < 4; k++) {
            int idx = e + k * nthreads;
            if (idx < Ee) { ss[k] = ei[idx]; dd[k] = ei[Ee + idx]; }
            else          { dd[k] = -1; }
        }
#pragma unroll
        for (int k = 0; k < 4; k++) {
            if (dd[k] >= 0) {
                int slot = atomicAdd(&g_cnt[dd[k]], 1);
                if (slot < CAP) g_adj[dd[k] * CAP + slot] = ss[k];
            }
        }
    }
    {
        const int GSB = (G < 128) ? G : 128;
        if (b < GSB) {
            float s = 0.f, q = 0.f;
            for (int n = b * 8 + w; n < Nv; n += GSB * 8) {
                float v = x[n * Tt + lane];
                s += v; q = fmaf(v, v, q);
            }
            sh[w][lane] = s; sh[w][32 + lane] = q;
            __syncthreads();
            if (tid < 64) {
                float v = 0.f;
#pragma unroll
                for (int i = 0; i < 8; i++) v += sh[i][tid];
                atomicAdd(&g_stat0[tid], v);
            }
        }
    }
    gsync();  // S1

    // ---- P2: layer-0 stats finish (per block) + normconv-0 ----
    if (tid < Tt) {
        float s = g_stat0[tid], q = g_stat0[32 + tid];
        float m = s / (float)Nv;
        float a = alpha[tid];
        float nsq = q + (float)Nv * m * m * (a * a - 2.f * a);
        float invn = sqrtf((float)Nv) * rsqrtf(nsq);
        sm[tid]   = a * m;
        smul[tid] = invn * scale[tid];
        ssh[tid]  = shift[tid];
    }
    if (tid < Cc * Kk) sW[tid] = convW[tid];
    if (tid < Cc)      sbias[tid] = convb[tid];
    __syncthreads();
    for (int node = gwarp; node < Nv; node += nwarps) {
        float v = x[node * Tt + lane];
        v = fmaf(v - sm[lane], smul[lane], ssh[lane]);
        g_xn[node * Tt + lane] = v;
        float win[Kk];
#pragma unroll
        for (int d = -PADc; d <= PADc; d++) {
            int si = lane + d;
            float u = __shfl_sync(0xffffffffu, v, si & 31);
            win[d + PADc] = (si >= 0 && si < Tt) ? u : 0.f;
        }
        float mx = -3.0e38f;
#pragma unroll
        for (int c = 0; c < Cc; c++) {
            float a2 = sbias[c];
#pragma unroll
            for (int k = 0; k < Kk; k++) a2 = fmaf(win[k], sW[c * Kk + k], a2);
            mx = fmaxf(mx, a2);
        }
        g_cm[node * Tt + lane] = mx;
    }
    gsync();  // S2

    // ---- P3: aggr-0 (+relu) -> g_x, fused layer-1 stats (work-stealing) ----
    if (b == 0 && tid < 64) g_stat0[tid] = 0.f;  // reset for next replay (post-S2: safe)
    {
        float4 s4 = make_float4(0.f, 0.f, 0.f, 0.f);
        float4 q4 = make_float4(0.f, 0.f, 0.f, 0.f);
        for (;;) {
            int nb;
            if (lane == 0) nb = atomicAdd(&g_ctrA, 1);
            nb = __shfl_sync(0xffffffffu, nb, 0);
            if (nb >= NUNITS) break;
            const int n0 = nb * 8 + grp * 2;
            const int n1 = n0 + 1;
            int d0 = g_cnt[n0]; if (d0 > CAP) d0 = CAP;
            int d1 = g_cnt[n1]; if (d1 > CAP) d1 = CAP;
            float4 acc0, acc1;
            gather4x2(d0, d1, n0 * CAP, n1 * CAP, sub, acc0, acc1);
            const float inv0 = 1.0f / (float)(d0 > 1 ? d0 : 1);
            const float inv1 = 1.0f / (float)(d1 > 1 ? d1 : 1);
            const float4 xn0 = *(const float4*)&g_xn[n0 * Tt + sub * 4];
            const float4 xn1 = *(const float4*)&g_xn[n1 * Tt + sub * 4];
            float4 v0, v1;
            v0.x = fmaxf(0.5f * fmaf(acc0.x, inv0, xn0.x), 0.f);
            v0.y = fmaxf(0.5f * fmaf(acc0.y, inv0, xn0.y), 0.f);
            v0.z = fmaxf(0.5f * fmaf(acc0.z, inv0, xn0.z), 0.f);
            v0.w = fmaxf(0.5f * fmaf(acc0.w, inv0, xn0.w), 0.f);
            v1.x = fmaxf(0.5f * fmaf(acc1.x, inv1, xn1.x), 0.f);
            v1.y = fmaxf(0.5f * fmaf(acc1.y, inv1, xn1.y), 0.f);
            v1.z = fmaxf(0.5f * fmaf(acc1.z, inv1, xn1.z), 0.f);
            v1.w = fmaxf(0.5f * fmaf(acc1.w, inv1, xn1.w), 0.f);
            *(float4*)&g_x[n0 * Tt + sub * 4] = v0;
            *(float4*)&g_x[n1 * Tt + sub * 4] = v1;
            s4.x += v0.x + v1.x; q4.x = fmaf(v0.x, v0.x, fmaf(v1.x, v1.x, q4.x));
            s4.y += v0.y + v1.y; q4.y = fmaf(v0.y, v0.y, fmaf(v1.y, v1.y, q4.y));
            s4.z += v0.z + v1.z; q4.z = fmaf(v0.z, v0.z, fmaf(v1.z, v1.z, q4.z));
            s4.w += v0.w + v1.w; q4.w = fmaf(v0.w, v0.w, fmaf(v1.w, v1.w, q4.w));
        }
        // reduce across the 4 groups (lanes with equal sub share t-range)
#pragma unroll
        for (int off = 8; off < 32; off <<= 1) {
            s4.x += __shfl_xor_sync(0xffffffffu, s4.x, off);
            s4.y += __shfl_xor_sync(0xffffffffu, s4.y, off);
            s4.z += __shfl_xor_sync(0xffffffffu, s4.z, off);
            s4.w += __shfl_xor_sync(0xffffffffu, s4.w, off);
            q4.x += __shfl_xor_sync(0xffffffffu, q4.x, off);
            q4.y += __shfl_xor_sync(0xffffffffu, q4.y, off);
            q4.z += __shfl_xor_sync(0xffffffffu, q4.z, off);
            q4.w += __shfl_xor_sync(0xffffffffu, q4.w, off);
        }
        if (lane < 8) {
            sh[w][lane * 4 + 0] = s4.x;  sh[w][32 + lane * 4 + 0] = q4.x;
            sh[w][lane * 4 + 1] = s4.y;  sh[w][32 + lane * 4 + 1] = q4.y;
            sh[w][lane * 4 + 2] = s4.z;  sh[w][32 + lane * 4 + 2] = q4.z;
            sh[w][lane * 4 + 3] = s4.w;  sh[w][32 + lane * 4 + 3] = q4.w;
        }
        __syncthreads();
        if (tid < 64) {
            float v = 0.f;
#pragma unroll
            for (int i = 0; i < 8; i++) v += sh[i][tid];
            atomicAdd(&g_stat1[tid], v);
        }
    }
    gsync();  // S3

    // ---- P4: layer-1 stats finish + normconv-1 (src = g_x) ----
    if (b == 0 && tid == 0) g_ctrA = 0;  // reset for next replay (post-S3: safe)
    if (tid < Tt) {
        float s = g_stat1[tid], q = g_stat1[32 + tid];
        float m = s / (float)Nv;
        float a = alpha[Tt + tid];
        float nsq = q + (float)Nv * m * m * (a * a - 2.f * a);
        float invn = sqrtf((float)Nv) * rsqrtf(nsq);
        sm[tid]   = a * m;
        smul[tid] = invn * scale[Tt + tid];
        ssh[tid]  = shift[Tt + tid];
    }
    if (tid < Cc * Kk) sW[tid] = convW[Cc * Kk + tid];
    if (tid < Cc)      sbias[tid] = convb[Cc + tid];
    __syncthreads();
    for (int node = gwarp; node < Nv; node += nwarps) {
        float v = g_x[node * Tt + lane];
        v = fmaf(v - sm[lane], smul[lane], ssh[lane]);
        g_xn[node * Tt + lane] = v;
        float win[Kk];
#pragma unroll
        for (int d = -PADc; d <= PADc; d++) {
            int si = lane + d;
            float u = __shfl_sync(0xffffffffu, v, si & 31);
            win[d + PADc] = (si >= 0 && si < Tt) ? u : 0.f;
        }
        float mx = -3.0e38f;
#pragma unroll
        for (int c = 0; c < Cc; c++) {
            float a2 = sbias[c];
#pragma unroll
            for (int k = 0; k < Kk; k++) a2 = fmaf(win[k], sW[c * Kk + k], a2);
            mx = fmaxf(mx, a2);
        }
        g_cm[node * Tt + lane] = mx;
    }
    gsync();  // S4

    // ---- P5: aggr-1 (+relu) + output head partials (work-stealing) ----
    if (b == 0 && tid < 64) g_stat1[tid] = 0.f;  // reset (post-S4: safe)
    {
        float p0 = 0.f, p1 = 0.f, p2 = 0.f;
        for (;;) {
            int nb;
            if (lane == 0) nb = atomicAdd(&g_ctrB, 1);
            nb = __shfl_sync(0xffffffffu, nb, 0);
            if (nb >= NUNITS) break;
            const int n0 = nb * 8 + grp * 2;
            const int n1 = n0 + 1;
            int d0 = g_cnt[n0]; if (d0 > CAP) d0 = CAP;
            int d1 = g_cnt[n1]; if (d1 > CAP) d1 = CAP;
            if (sub == 0) { g_cnt[n0] = 0; g_cnt[n1] = 0; }  // last use: reset
            float4 acc0, acc1;
            gather4x2(d0, d1, n0 * CAP, n1 * CAP, sub, acc0, acc1);
            const float inv0 = 1.0f / (float)(d0 > 1 ? d0 : 1);
            const float inv1 = 1.0f / (float)(d1 > 1 ? d1 : 1);
            const float4 xn0 = *(const float4*)&g_xn[n0 * Tt + sub * 4];
            const float4 xn1 = *(const float4*)&g_xn[n1 * Tt + sub * 4];
            float rs0 = fmaxf(0.5f * fmaf(acc0.x, inv0, xn0.x), 0.f)
                      + fmaxf(0.5f * fmaf(acc0.y, inv0, xn0.y), 0.f)
                      + fmaxf(0.5f * fmaf(acc0.z, inv0, xn0.z), 0.f)
                      + fmaxf(0.5f * fmaf(acc0.w, inv0, xn0.w), 0.f);
            float rs1 = fmaxf(0.5f * fmaf(acc1.x, inv1, xn1.x), 0.f)
                      + fmaxf(0.5f * fmaf(acc1.y, inv1, xn1.y), 0.f)
                      + fmaxf(0.5f * fmaf(acc1.z, inv1, xn1.z), 0.f)
                      + fmaxf(0.5f * fmaf(acc1.w, inv1, xn1.w), 0.f);
            // rowsums within the 8-lane group
            rs0 += __shfl_xor_sync(0xffffffffu, rs0, 1);
            rs0 += __shfl_xor_sync(0xffffffffu, rs0, 2);
            rs0 += __shfl_xor_sync(0xffffffffu, rs0, 4);
            rs1 += __shfl_xor_sync(0xffffffffu, rs1, 1);
            rs1 += __shfl_xor_sync(0xffffffffu, rs1, 2);
            rs1 += __shfl_xor_sync(0xffffffffu, rs1, 4);
            if (sub == 0) {
                p0 = fmaf(Wout[n0], rs0, fmaf(Wout[n1], rs1, p0));
                p1 = fmaf(Wout[Nv + n0], rs0, fmaf(Wout[Nv + n1], rs1, p1));
                p2 = fmaf(Wout[2 * Nv + n0], rs0, fmaf(Wout[2 * Nv + n1], rs1, p2));
            }
        }
        // sum the 4 group-leader lanes (others hold 0)
#pragma unroll
        for (int off = 8; off < 32; off <<= 1) {
            p0 += __shfl_xor_sync(0xffffffffu, p0, off);
            p1 += __shfl_xor_sync(0xffffffffu, p1, off);
            p2 += __shfl_xor_sync(0xffffffffu, p2, off);
        }
        if (lane == 0) { shp[w][0] = p0; shp[w][1] = p1; shp[w][2] = p2; }
        __syncthreads();
        if (tid < 3) {
            float v = 0.f;
#pragma unroll
            for (int i = 0; i < 8; i++) v += shp[i][tid];
            atomicAdd(&g_out3[tid], v);
        }
    }
    gsync();  // S5

    // ---- P6: write logits + reset remaining replay state ----
    if (b == 0) {
        if (tid < 3) {
            out[tid] = g_out3[tid] + bout[tid];
            g_out3[tid] = 0.f;   // reset after read
        }
        if (tid == 32) g_ctrB = 0;  // reset (post-S5: safe)
    }
}

// ---------------- launch ---------------------------------------------------
extern "C" void kernel_launch(void* const* d_in, const int* in_sizes, int n_in,
                              void* d_out, int out_size) {
    const float* x     = (const float*)d_in[0];
    const float* convW = (const float*)d_in[1];
    const float* convb = (const float*)d_in[2];
    const float* alpha = (const float*)d_in[3];
    const float* scale = (const float*)d_in[4];
    const float* shift = (const float*)d_in[5];
    const float* Wout  = (const float*)d_in[6];
    const float* bout  = (const float*)d_in[7];
    const int*   ei    = (const int*)d_in[8];
    float*       out   = (float*)d_out;

    int dev = 0;
    cudaGetDevice(&dev);
    int sms = 0;
    cudaDeviceGetAttribute(&sms, cudaDevAttrMultiProcessorCount, dev);
    int bpm = 0;
    cudaOccupancyMaxActiveBlocksPerMultiprocessor(&bpm, sage_fused, NTH, 0);
    if (bpm < 1) bpm = 1;
    int G = sms * bpm;
    if (G > MAXG) G = MAXG;

    void* args[10] = {
        (void*)&x, (void*)&convW, (void*)&convb, (void*)&alpha, (void*)&scale,
        (void*)&shift, (void*)&Wout, (void*)&bout, (void*)&ei, (void*)&out
    };
    cudaLaunchCooperativeKernel((const void*)sage_fused, dim3(G), dim3(NTH),
                                args, 0, (cudaStream_t)0);
}